// round 3
// baseline (speedup 1.0000x reference)
#include <cuda_runtime.h>
#include <cuda_bf16.h>
#include <math_constants.h>

// Problem constants
#define Bn 16
#define Sn 2048
#define Dn 768
#define D4 192                 // Dn / 4 (float4 per row)
#define ROWS_PER_WARP 16
#define CHUNKS_PER_B (Sn / ROWS_PER_WARP)      // 128
#define NWARPS (Bn * CHUNKS_PER_B)             // 2048
#define NORM_CONST 0.0360843918243516127f      // 1/sqrt(768)

// ---------------- scratch (no allocations allowed) ----------------
__device__ float g_q0[Bn * Dn];
__device__ float g_qk[Bn * Dn];
__device__ float g_pm[NWARPS];
__device__ float g_pl[NWARPS];
__device__ float g_pacc[(size_t)NWARPS * Dn];   // ~6.3 MB
__device__ float g_c[Bn * Dn];

// ---------------- helpers ----------------
__device__ __forceinline__ float warp_sum(float v) {
    #pragma unroll
    for (int off = 16; off > 0; off >>= 1)
        v += __shfl_xor_sync(0xffffffffu, v, off);
    return v;
}

// ---------------- K1 / K5: out[b][e] = sum_d W[e][d] * X[b*ldx + d]
// All 16 batch vectors cached in smem; each warp handles one output row e,
// so W is streamed from DRAM exactly once across the whole grid.
__global__ void __launch_bounds__(256) matvec_allb(
    float* __restrict__ out, const float* __restrict__ W,
    const float* __restrict__ X, long long ldx)
{
    __shared__ float xs[Bn * Dn];   // 48 KB (exactly the static limit)
    int tid = threadIdx.x;
    for (int idx = tid; idx < Bn * Dn; idx += 256) {
        int b = idx / Dn;
        int d = idx - b * Dn;
        xs[idx] = X[(size_t)b * (size_t)ldx + d];
    }
    __syncthreads();

    int warp = tid >> 5, lane = tid & 31;
    int e = blockIdx.x * 8 + warp;          // 96 blocks * 8 warps = 768 rows

    const float4* wr = (const float4*)(W + (size_t)e * Dn);
    float4 wf[6];
    #pragma unroll
    for (int i = 0; i < 6; i++) wf[i] = wr[i * 32 + lane];

    const float4* xs4 = (const float4*)xs;
    float acc[Bn];
    #pragma unroll
    for (int b = 0; b < Bn; b++) acc[b] = 0.f;

    #pragma unroll
    for (int i = 0; i < 6; i++) {
        float4 w = wf[i];
        #pragma unroll
        for (int b = 0; b < Bn; b++) {
            float4 x = xs4[b * D4 + i * 32 + lane];
            acc[b] = fmaf(w.x, x.x, fmaf(w.y, x.y, fmaf(w.z, x.z, fmaf(w.w, x.w, acc[b]))));
        }
    }
    #pragma unroll
    for (int b = 0; b < Bn; b++) {
        float v = warp_sum(acc[b]);
        if (lane == 0) out[b * Dn + e] = v;
    }
}

// ---------------- zero qk for the atomic combine
__global__ void zero_buf(float* __restrict__ p, int n) {
    int i = blockIdx.x * 256 + threadIdx.x;
    if (i < n) p[i] = 0.f;
}

// ---------------- K2: qk[b][d] = sum_e q0[b][e] * Wk[e][d]
// grid (3 d-chunks, 16 e-chunks); Wk streamed from DRAM exactly once.
__global__ void __launch_bounds__(256) qk_kernel(
    float* __restrict__ qk, const float* __restrict__ Wk,
    const float* __restrict__ q0)
{
    __shared__ float q0s[Bn * 48];
    int t = threadIdx.x;
    int e0 = blockIdx.y * 48;
    for (int idx = t; idx < Bn * 48; idx += 256) {
        int b = idx / 48, eo = idx - b * 48;
        q0s[idx] = q0[b * Dn + e0 + eo];
    }
    __syncthreads();

    int d = blockIdx.x * 256 + t;
    float acc[Bn];
    #pragma unroll
    for (int b = 0; b < Bn; b++) acc[b] = 0.f;

    for (int eo = 0; eo < 48; eo++) {
        float w = Wk[(size_t)(e0 + eo) * Dn + d];
        #pragma unroll
        for (int b = 0; b < Bn; b++)
            acc[b] = fmaf(q0s[b * 48 + eo], w, acc[b]);
    }
    #pragma unroll
    for (int b = 0; b < Bn; b++)
        atomicAdd(&qk[b * Dn + d], acc[b]);
}

// ---------------- K3: the streaming pass. One warp = 16 rows of one batch.
// Online softmax with a 768-wide register accumulator; double-buffered loads.
__global__ void __launch_bounds__(32) attn_partial(
    const float* __restrict__ b_in, const float* __restrict__ qk)
{
    int g = blockIdx.x;                 // 0..2047 global warp id
    int b = g >> 7;                     // / CHUNKS_PER_B
    int j = g & (CHUNKS_PER_B - 1);
    int lane = threadIdx.x;

    const float4* qkv = (const float4*)(qk + b * Dn);
    float4 qf[6];
    #pragma unroll
    for (int i = 0; i < 6; i++) qf[i] = qkv[i * 32 + lane];

    const float4* xb = (const float4*)(b_in + ((size_t)b * Sn + (size_t)j * ROWS_PER_WARP) * Dn);

    float m = -CUDART_INF_F;
    float l = 0.f;
    float4 acc[6];
    #pragma unroll
    for (int i = 0; i < 6; i++) acc[i] = make_float4(0.f, 0.f, 0.f, 0.f);

    float4 cur[6];
    #pragma unroll
    for (int i = 0; i < 6; i++) cur[i] = xb[i * 32 + lane];

    #pragma unroll
    for (int r = 0; r < ROWS_PER_WARP; r++) {
        float4 nxt[6];
        if (r < ROWS_PER_WARP - 1) {
            const float4* rn = xb + (size_t)(r + 1) * D4;
            #pragma unroll
            for (int i = 0; i < 6; i++) nxt[i] = rn[i * 32 + lane];
        }
        float dot = 0.f;
        #pragma unroll
        for (int i = 0; i < 6; i++) {
            dot = fmaf(qf[i].x, cur[i].x, dot);
            dot = fmaf(qf[i].y, cur[i].y, dot);
            dot = fmaf(qf[i].z, cur[i].z, dot);
            dot = fmaf(qf[i].w, cur[i].w, dot);
        }
        dot = warp_sum(dot);
        float score = dot * NORM_CONST;

        float mn = fmaxf(m, score);
        float corr = __expf(m - mn);        // exp(-inf)=0 on first row
        float w = __expf(score - mn);
        l = l * corr + w;
        #pragma unroll
        for (int i = 0; i < 6; i++) {
            acc[i].x = fmaf(w, cur[i].x, acc[i].x * corr);
            acc[i].y = fmaf(w, cur[i].y, acc[i].y * corr);
            acc[i].z = fmaf(w, cur[i].z, acc[i].z * corr);
            acc[i].w = fmaf(w, cur[i].w, acc[i].w * corr);
        }
        m = mn;
        if (r < ROWS_PER_WARP - 1) {
            #pragma unroll
            for (int i = 0; i < 6; i++) cur[i] = nxt[i];
        }
    }

    if (lane == 0) { g_pm[g] = m; g_pl[g] = l; }
    float4* pa = (float4*)(g_pacc + (size_t)g * Dn);
    #pragma unroll
    for (int i = 0; i < 6; i++) pa[i * 32 + lane] = acc[i];
}

// ---------------- K4: split-softmax combine -> c[b][d]
__global__ void __launch_bounds__(256) combine_kernel(float* __restrict__ c)
{
    int b = blockIdx.y;
    int d = blockIdx.x * 256 + threadIdx.x;
    const float* pm = g_pm + b * CHUNKS_PER_B;
    const float* pl = g_pl + b * CHUNKS_PER_B;

    float M = -CUDART_INF_F;
    #pragma unroll 8
    for (int jj = 0; jj < CHUNKS_PER_B; jj++) M = fmaxf(M, pm[jj]);

    float L = 0.f, s = 0.f;
    for (int jj = 0; jj < CHUNKS_PER_B; jj++) {
        float ef = __expf(pm[jj] - M);
        L = fmaf(ef, pl[jj], L);
        s = fmaf(ef, g_pacc[((size_t)(b * CHUNKS_PER_B + jj)) * Dn + d], s);
    }
    c[b * Dn + d] = s / L;
}

// ---------------- launch ----------------
extern "C" void kernel_launch(void* const* d_in, const int* in_sizes, int n_in,
                              void* d_out, int out_size)
{
    const float* b_in = (const float*)d_in[0];
    // d_in[1] = mask (int64) — provably irrelevant: it masks whole QUERY rows
    // and query row 0 is always unmasked; the output only uses query row 0.
    const float* Wq = (const float*)d_in[2];
    const float* Wk = (const float*)d_in[3];
    const float* Wv = (const float*)d_in[4];
    float* out = (float*)d_out;

    float* q0; cudaGetSymbolAddress((void**)&q0, g_q0);
    float* qk; cudaGetSymbolAddress((void**)&qk, g_qk);
    float* cc; cudaGetSymbolAddress((void**)&cc, g_c);

    // 1) q0 = x0 @ Wq^T
    matvec_allb<<<96, 256>>>(q0, Wq, b_in, (long long)Sn * Dn);
    // 2) qk = Wk^T q0  (zero + atomic partial sums)
    zero_buf<<<(Bn * Dn + 255) / 256, 256>>>(qk, Bn * Dn);
    qk_kernel<<<dim3(3, 16), 256>>>(qk, Wk, q0);
    // 3) streaming online-softmax weighted sum over all of b_in
    attn_partial<<<NWARPS, 32>>>(b_in, qk);
    // 4) merge partials
    combine_kernel<<<dim3(3, Bn), 256>>>(cc);
    // 5) out = Wv c
    matvec_allb<<<96, 256>>>(out, Wv, cc, Dn);
}

// round 6
// speedup vs baseline: 1.7758x; 1.7758x over previous
#include <cstdint>
#include <cuda_runtime.h>
#include <cuda_bf16.h>
#include <math_constants.h>

#define Bn 16
#define Sn 2048
#define Dn 768
#define D4 192                       // Dn/4
#define NORM_CONST 0.0360843918243516127f  // 1/sqrt(768)

// attn pipeline geometry
#define CHUNK_ROWS 128
#define CHUNKS_PER_B (Sn / CHUNK_ROWS)     // 16
#define NPART (Bn * CHUNKS_PER_B)          // 256 partials
#define ATT_STAGES 4
#define RPS 8                              // rows per stage
#define STAGE_F4 (RPS * D4)                // 1536 float4
#define STAGE_BYTES (STAGE_F4 * 16)        // 24576
#define NSTAGE_ITERS (CHUNK_ROWS / RPS)    // 16

// ---------------- scratch ----------------
__device__ float g_qk[Bn * Dn];
__device__ float g_pm[NPART];
__device__ float g_pl[NPART];
__device__ float g_pacc[(size_t)NPART * Dn];   // 786 KB
__device__ float g_c[Bn * Dn];

// ---------------- helpers ----------------
__device__ __forceinline__ float warp_sum(float v) {
    #pragma unroll
    for (int off = 16; off > 0; off >>= 1)
        v += __shfl_xor_sync(0xffffffffu, v, off);
    return v;
}

__device__ __forceinline__ void cp_async16(unsigned int dst, const void* src) {
    asm volatile("cp.async.cg.shared.global [%0], [%1], 16;" :: "r"(dst), "l"(src));
}

// ============ K1: fused q0 = Wq x0, qk += Wk^T q0 (per e-tile, atomic) ============
// grid 96 blocks; e-tile = 8 rows; Wq and Wk each streamed from DRAM exactly once.
__global__ void __launch_bounds__(256) fused_q0qk(
    float* __restrict__ qk, const float* __restrict__ Wq,
    const float* __restrict__ Wk, const float* __restrict__ b_in)
{
    extern __shared__ float xs[];             // 48 KB: x0 for all 16 batches
    __shared__ float q0s[8 * Bn];             // q0 tile [e_local][b]
    int tid = threadIdx.x, warp = tid >> 5, lane = tid & 31;
    int e0 = blockIdx.x * 8;

    for (int idx = tid; idx < Bn * Dn; idx += 256) {
        int b = idx / Dn, d = idx - b * Dn;
        xs[idx] = b_in[(size_t)b * Sn * Dn + d];   // row 0 of each batch
    }
    __syncthreads();

    // phase 1: warp w computes q0[e0+w][b] for all b
    {
        int e = e0 + warp;
        const float4* wr = (const float4*)(Wq + (size_t)e * Dn);
        float4 wf[6];
        #pragma unroll
        for (int i = 0; i < 6; i++) wf[i] = wr[i * 32 + lane];
        const float4* xs4 = (const float4*)xs;
        float acc[Bn];
        #pragma unroll
        for (int b = 0; b < Bn; b++) acc[b] = 0.f;
        #pragma unroll
        for (int i = 0; i < 6; i++) {
            float4 w = wf[i];
            #pragma unroll
            for (int b = 0; b < Bn; b++) {
                float4 x = xs4[b * D4 + i * 32 + lane];
                acc[b] = fmaf(w.x, x.x, fmaf(w.y, x.y, fmaf(w.z, x.z, fmaf(w.w, x.w, acc[b]))));
            }
        }
        #pragma unroll
        for (int b = 0; b < Bn; b++) {
            float v = warp_sum(acc[b]);
            if (lane == 0) q0s[warp * Bn + b] = v;
        }
    }
    __syncthreads();

    // phase 2: partial qk[b][d] += sum_{e in tile} q0[e][b] * Wk[e][d]
    {
        float a0[Bn], a1[Bn], a2[Bn];
        #pragma unroll
        for (int b = 0; b < Bn; b++) { a0[b] = a1[b] = a2[b] = 0.f; }
        #pragma unroll
        for (int e = 0; e < 8; e++) {
            const float* wr = Wk + (size_t)(e0 + e) * Dn;
            float w0 = wr[tid], w1 = wr[tid + 256], w2 = wr[tid + 512];
            #pragma unroll
            for (int b = 0; b < Bn; b++) {
                float q = q0s[e * Bn + b];
                a0[b] = fmaf(q, w0, a0[b]);
                a1[b] = fmaf(q, w1, a1[b]);
                a2[b] = fmaf(q, w2, a2[b]);
            }
        }
        #pragma unroll
        for (int b = 0; b < Bn; b++) {
            atomicAdd(&qk[b * Dn + tid],       a0[b]);
            atomicAdd(&qk[b * Dn + tid + 256], a1[b]);
            atomicAdd(&qk[b * Dn + tid + 512], a2[b]);
        }
    }
}

// ============ K2: streaming online-softmax, cp.async 4-stage pipeline ============
// 256 blocks x 256 threads; block = (batch b, chunk c of 128 rows).
__global__ void __launch_bounds__(256, 2) attn_stream(
    const float* __restrict__ b_in, const float* __restrict__ qk)
{
    extern __shared__ float4 smem4[];          // 96 KB: 4 stages x 8 rows
    __shared__ float msm[8], lsm[8];
    int tid = threadIdx.x, warp = tid >> 5, lane = tid & 31;
    int b = blockIdx.x >> 4, c = blockIdx.x & (CHUNKS_PER_B - 1);

    const float4* qkv = (const float4*)(qk + b * Dn);
    float4 qf[6];
    #pragma unroll
    for (int i = 0; i < 6; i++) qf[i] = qkv[i * 32 + lane];

    const float4* xb4 = (const float4*)b_in + ((size_t)b * Sn + (size_t)c * CHUNK_ROWS) * D4;
    unsigned int sbase = (unsigned int)__cvta_generic_to_shared(smem4);

    // prologue: fill stages 0..2
    #pragma unroll
    for (int s = 0; s < ATT_STAGES - 1; s++) {
        const float4* src = xb4 + (size_t)s * STAGE_F4;
        unsigned int dst = sbase + s * STAGE_BYTES;
        #pragma unroll
        for (int i = 0; i < 6; i++) {
            int idx = i * 256 + tid;
            cp_async16(dst + idx * 16, src + idx);
        }
        asm volatile("cp.async.commit_group;");
    }

    float m = -CUDART_INF_F, l = 0.f;
    float4 acc[6];
    #pragma unroll
    for (int i = 0; i < 6; i++) acc[i] = make_float4(0.f, 0.f, 0.f, 0.f);

    for (int t = 0; t < NSTAGE_ITERS; t++) {
        if (t + ATT_STAGES - 1 < NSTAGE_ITERS) {
            int sn = t + ATT_STAGES - 1;
            const float4* src = xb4 + (size_t)sn * STAGE_F4;
            unsigned int dst = sbase + (sn & (ATT_STAGES - 1)) * STAGE_BYTES;
            #pragma unroll
            for (int i = 0; i < 6; i++) {
                int idx = i * 256 + tid;
                cp_async16(dst + idx * 16, src + idx);
            }
        }
        asm volatile("cp.async.commit_group;");
        asm volatile("cp.async.wait_group 3;");
        __syncthreads();

        // warp w consumes row w of stage t
        const float4* row = smem4 + (size_t)(t & (ATT_STAGES - 1)) * STAGE_F4 + warp * D4;
        float4 cur[6];
        #pragma unroll
        for (int i = 0; i < 6; i++) cur[i] = row[i * 32 + lane];

        float dot = 0.f;
        #pragma unroll
        for (int i = 0; i < 6; i++) {
            dot = fmaf(qf[i].x, cur[i].x, dot);
            dot = fmaf(qf[i].y, cur[i].y, dot);
            dot = fmaf(qf[i].z, cur[i].z, dot);
            dot = fmaf(qf[i].w, cur[i].w, dot);
        }
        float score = warp_sum(dot) * NORM_CONST;

        float mn = fmaxf(m, score);
        float corr = __expf(m - mn);       // first row: exp(-inf)=0
        float w = __expf(score - mn);
        l = l * corr + w;
        #pragma unroll
        for (int i = 0; i < 6; i++) {
            acc[i].x = fmaf(w, cur[i].x, acc[i].x * corr);
            acc[i].y = fmaf(w, cur[i].y, acc[i].y * corr);
            acc[i].z = fmaf(w, cur[i].z, acc[i].z * corr);
            acc[i].w = fmaf(w, cur[i].w, acc[i].w * corr);
        }
        m = mn;
        __syncthreads();   // protect stage before next refill
    }

    // in-block merge of 8 warp partials -> 1 block partial
    float4* accsm = smem4;   // reuse stage memory (all stages consumed; sync above)
    #pragma unroll
    for (int i = 0; i < 6; i++) accsm[warp * D4 + i * 32 + lane] = acc[i];
    if (lane == 0) { msm[warp] = m; lsm[warp] = l; }
    __syncthreads();

    if (tid < D4) {
        float M = -CUDART_INF_F;
        #pragma unroll
        for (int w = 0; w < 8; w++) M = fmaxf(M, msm[w]);
        float L = 0.f;
        float4 s = make_float4(0.f, 0.f, 0.f, 0.f);
        #pragma unroll
        for (int w = 0; w < 8; w++) {
            float ef = __expf(msm[w] - M);
            L = fmaf(ef, lsm[w], L);
            float4 a = accsm[w * D4 + tid];
            s.x = fmaf(ef, a.x, s.x);
            s.y = fmaf(ef, a.y, s.y);
            s.z = fmaf(ef, a.z, s.z);
            s.w = fmaf(ef, a.w, s.w);
        }
        ((float4*)g_pacc)[(size_t)blockIdx.x * D4 + tid] = s;
        if (tid == 0) { g_pm[blockIdx.x] = M; g_pl[blockIdx.x] = L; }
    }
}

// ============ K3: split-softmax combine (16 partials/batch) ============
__global__ void __launch_bounds__(256) combine2(float* __restrict__ c)
{
    int b = blockIdx.y;
    int d = blockIdx.x * 256 + threadIdx.x;
    const float* pm = g_pm + b * CHUNKS_PER_B;
    const float* pl = g_pl + b * CHUNKS_PER_B;

    float M = -CUDART_INF_F;
    #pragma unroll
    for (int j = 0; j < CHUNKS_PER_B; j++) M = fmaxf(M, pm[j]);

    float L = 0.f, s = 0.f;
    #pragma unroll
    for (int j = 0; j < CHUNKS_PER_B; j++) {
        float ef = __expf(pm[j] - M);
        L = fmaf(ef, pl[j], L);
        s = fmaf(ef, g_pacc[((size_t)(b * CHUNKS_PER_B + j)) * Dn + d], s);
    }
    c[b * Dn + d] = s / L;
}

// ============ K4: out[b][e] = Wv[e][:] . c[b][:]  (d-split x2 per e-row) ============
// 192 blocks x 8 warps: warp (w&3) = e-row, (w>>2) = d-half; Wv streamed once.
__global__ void __launch_bounds__(256) matvec_wv(
    float* __restrict__ out, const float* __restrict__ W,
    const float* __restrict__ X)
{
    extern __shared__ float xs[];             // 48 KB: c for all 16 batches
    __shared__ float psum[8][Bn];
    int tid = threadIdx.x, warp = tid >> 5, lane = tid & 31;

    for (int idx = tid; idx < Bn * Dn; idx += 256) xs[idx] = X[idx];
    __syncthreads();

    int e = blockIdx.x * 4 + (warp & 3);
    int half = warp >> 2;
    const float4* wr = (const float4*)(W + (size_t)e * Dn) + half * 96;
    float4 wf[3];
    #pragma unroll
    for (int i = 0; i < 3; i++) wf[i] = wr[i * 32 + lane];

    const float4* xs4 = (const float4*)xs;
    float acc[Bn];
    #pragma unroll
    for (int b = 0; b < Bn; b++) acc[b] = 0.f;
    #pragma unroll
    for (int i = 0; i < 3; i++) {
        float4 w = wf[i];
        #pragma unroll
        for (int b = 0; b < Bn; b++) {
            float4 x = xs4[b * D4 + half * 96 + i * 32 + lane];
            acc[b] = fmaf(w.x, x.x, fmaf(w.y, x.y, fmaf(w.z, x.z, fmaf(w.w, x.w, acc[b]))));
        }
    }
    #pragma unroll
    for (int b = 0; b < Bn; b++) {
        float v = warp_sum(acc[b]);
        if (lane == 0) psum[warp][b] = v;
    }
    __syncthreads();

    if (tid < 64) {
        int el = tid >> 4, b = tid & 15;
        out[b * Dn + blockIdx.x * 4 + el] = psum[el][b] + psum[el + 4][b];
    }
}

// ---------------- launch ----------------
extern "C" void kernel_launch(void* const* d_in, const int* in_sizes, int n_in,
                              void* d_out, int out_size)
{
    const float* b_in = (const float*)d_in[0];
    // d_in[1] = mask (int64): masks whole QUERY rows only; query row 0 is always
    // unmasked and the output only uses query row 0 -> mask is irrelevant.
    const float* Wq = (const float*)d_in[2];
    const float* Wk = (const float*)d_in[3];
    const float* Wv = (const float*)d_in[4];
    float* out = (float*)d_out;

    float* qk; cudaGetSymbolAddress((void**)&qk, g_qk);
    float* cc; cudaGetSymbolAddress((void**)&cc, g_c);

    cudaFuncSetAttribute(fused_q0qk, cudaFuncAttributeMaxDynamicSharedMemorySize, 49152);
    cudaFuncSetAttribute(attn_stream, cudaFuncAttributeMaxDynamicSharedMemorySize, ATT_STAGES * STAGE_BYTES);
    cudaFuncSetAttribute(matvec_wv, cudaFuncAttributeMaxDynamicSharedMemorySize, 49152);

    cudaMemsetAsync(qk, 0, Bn * Dn * sizeof(float), 0);
    fused_q0qk<<<96, 256, 49152>>>(qk, Wq, Wk, b_in);
    attn_stream<<<NPART, 256, ATT_STAGES * STAGE_BYTES>>>(b_in, qk);
    combine2<<<dim3(3, Bn), 256>>>(cc);
    matvec_wv<<<192, 256, 49152>>>(out, Wv, cc);
}

// round 7
// speedup vs baseline: 2.2532x; 1.2689x over previous
#include <cstdint>
#include <cuda_runtime.h>
#include <cuda_bf16.h>
#include <math_constants.h>

#define Bn 16
#define Sn 2048
#define Dn 768
#define D4 192                       // Dn/4
#define NORM_CONST 0.0360843918243516127f  // 1/sqrt(768)

// attn pipeline geometry
#define CHUNK_ROWS 128
#define CHUNKS_PER_B (Sn / CHUNK_ROWS)     // 16
#define NPART (Bn * CHUNKS_PER_B)          // 256 partials
#define ATT_STAGES 4
#define RPS 8                              // rows per stage
#define STAGE_F4 (RPS * D4)                // 1536 float4
#define STAGE_BYTES (STAGE_F4 * 16)        // 24576
#define NSTAGE_ITERS (CHUNK_ROWS / RPS)    // 16

// ---------------- scratch ----------------
__device__ float g_qk[Bn * Dn];
__device__ float g_pm[NPART];
__device__ float g_pl[NPART];
__device__ float g_pacc[(size_t)NPART * Dn];   // 786 KB
__device__ float g_c[Bn * Dn];

// ---------------- helpers ----------------
__device__ __forceinline__ float warp_sum(float v) {
    #pragma unroll
    for (int off = 16; off > 0; off >>= 1)
        v += __shfl_xor_sync(0xffffffffu, v, off);
    return v;
}

__device__ __forceinline__ void cp_async16(unsigned int dst, const void* src) {
    asm volatile("cp.async.cg.shared.global [%0], [%1], 16;" :: "r"(dst), "l"(src));
}
__device__ __forceinline__ void cp_commit() {
    asm volatile("cp.async.commit_group;");
}
__device__ __forceinline__ void cp_wait_all() {
    asm volatile("cp.async.wait_group 0;");
}

// ============ K1: fused q0 = Wq x0, qk += Wk^T q0 (per e-tile, atomic) ============
// grid 96 blocks; e-tile = 8 rows; Wq and Wk each streamed from DRAM exactly once.
// x0 preload via cp.async float4 (12/thread), overlapped with Wq register loads.
__global__ void __launch_bounds__(256) fused_q0qk(
    float* __restrict__ qk, const float* __restrict__ Wq,
    const float* __restrict__ Wk, const float* __restrict__ b_in)
{
    extern __shared__ float xs[];             // 48 KB: x0 for all 16 batches
    __shared__ float q0s[8 * Bn];             // q0 tile [e_local][b]
    int tid = threadIdx.x, warp = tid >> 5, lane = tid & 31;
    int e0 = blockIdx.x * 8;

    // async preload of the 16 x0 rows (each row: 192 float4, contiguous)
    {
        unsigned int sb = (unsigned int)__cvta_generic_to_shared(xs);
        const float4* src4 = (const float4*)b_in;
        #pragma unroll
        for (int i = 0; i < 12; i++) {
            int idx = i * 256 + tid;          // 0..3071
            int b = idx / D4, d4 = idx - b * D4;
            cp_async16(sb + idx * 16, src4 + (size_t)b * Sn * D4 + d4);
        }
        cp_commit();
    }

    // overlap: load this warp's Wq row into registers
    int e = e0 + warp;
    const float4* wr = (const float4*)(Wq + (size_t)e * Dn);
    float4 wf[6];
    #pragma unroll
    for (int i = 0; i < 6; i++) wf[i] = wr[i * 32 + lane];

    cp_wait_all();
    __syncthreads();

    // phase 1: warp w computes q0[e0+w][b] for all b
    {
        const float4* xs4 = (const float4*)xs;
        float acc[Bn];
        #pragma unroll
        for (int b = 0; b < Bn; b++) acc[b] = 0.f;
        #pragma unroll
        for (int i = 0; i < 6; i++) {
            float4 w = wf[i];
            #pragma unroll
            for (int b = 0; b < Bn; b++) {
                float4 x = xs4[b * D4 + i * 32 + lane];
                acc[b] = fmaf(w.x, x.x, fmaf(w.y, x.y, fmaf(w.z, x.z, fmaf(w.w, x.w, acc[b]))));
            }
        }
        #pragma unroll
        for (int b = 0; b < Bn; b++) {
            float v = warp_sum(acc[b]);
            if (lane == 0) q0s[warp * Bn + b] = v;
        }
    }
    __syncthreads();

    // phase 2: partial qk[b][d] += sum_{e in tile} q0[e][b] * Wk[e][d]
    {
        float a0[Bn], a1[Bn], a2[Bn];
        #pragma unroll
        for (int b = 0; b < Bn; b++) { a0[b] = a1[b] = a2[b] = 0.f; }
        #pragma unroll
        for (int ee = 0; ee < 8; ee++) {
            const float* wkr = Wk + (size_t)(e0 + ee) * Dn;
            float w0 = wkr[tid], w1 = wkr[tid + 256], w2 = wkr[tid + 512];
            #pragma unroll
            for (int b = 0; b < Bn; b++) {
                float q = q0s[ee * Bn + b];
                a0[b] = fmaf(q, w0, a0[b]);
                a1[b] = fmaf(q, w1, a1[b]);
                a2[b] = fmaf(q, w2, a2[b]);
            }
        }
        #pragma unroll
        for (int b = 0; b < Bn; b++) {
            atomicAdd(&qk[b * Dn + tid],       a0[b]);
            atomicAdd(&qk[b * Dn + tid + 256], a1[b]);
            atomicAdd(&qk[b * Dn + tid + 512], a2[b]);
        }
    }
}

// ============ K2: streaming online-softmax, cp.async 4-stage pipeline ============
// 256 blocks x 256 threads; block = (batch b, chunk c of 128 rows).
__global__ void __launch_bounds__(256, 2) attn_stream(
    const float* __restrict__ b_in, const float* __restrict__ qk)
{
    extern __shared__ float4 smem4[];          // 96 KB: 4 stages x 8 rows
    __shared__ float msm[8], lsm[8];
    int tid = threadIdx.x, warp = tid >> 5, lane = tid & 31;
    int b = blockIdx.x >> 4, c = blockIdx.x & (CHUNKS_PER_B - 1);

    const float4* qkv = (const float4*)(qk + b * Dn);
    float4 qf[6];
    #pragma unroll
    for (int i = 0; i < 6; i++) qf[i] = qkv[i * 32 + lane];

    const float4* xb4 = (const float4*)b_in + ((size_t)b * Sn + (size_t)c * CHUNK_ROWS) * D4;
    unsigned int sbase = (unsigned int)__cvta_generic_to_shared(smem4);

    // prologue: fill stages 0..2
    #pragma unroll
    for (int s = 0; s < ATT_STAGES - 1; s++) {
        const float4* src = xb4 + (size_t)s * STAGE_F4;
        unsigned int dst = sbase + s * STAGE_BYTES;
        #pragma unroll
        for (int i = 0; i < 6; i++) {
            int idx = i * 256 + tid;
            cp_async16(dst + idx * 16, src + idx);
        }
        cp_commit();
    }

    float m = -CUDART_INF_F, l = 0.f;
    float4 acc[6];
    #pragma unroll
    for (int i = 0; i < 6; i++) acc[i] = make_float4(0.f, 0.f, 0.f, 0.f);

    for (int t = 0; t < NSTAGE_ITERS; t++) {
        if (t + ATT_STAGES - 1 < NSTAGE_ITERS) {
            int sn = t + ATT_STAGES - 1;
            const float4* src = xb4 + (size_t)sn * STAGE_F4;
            unsigned int dst = sbase + (sn & (ATT_STAGES - 1)) * STAGE_BYTES;
            #pragma unroll
            for (int i = 0; i < 6; i++) {
                int idx = i * 256 + tid;
                cp_async16(dst + idx * 16, src + idx);
            }
        }
        cp_commit();
        asm volatile("cp.async.wait_group 3;");
        __syncthreads();

        // warp w consumes row w of stage t
        const float4* row = smem4 + (size_t)(t & (ATT_STAGES - 1)) * STAGE_F4 + warp * D4;
        float4 cur[6];
        #pragma unroll
        for (int i = 0; i < 6; i++) cur[i] = row[i * 32 + lane];

        float dot = 0.f;
        #pragma unroll
        for (int i = 0; i < 6; i++) {
            dot = fmaf(qf[i].x, cur[i].x, dot);
            dot = fmaf(qf[i].y, cur[i].y, dot);
            dot = fmaf(qf[i].z, cur[i].z, dot);
            dot = fmaf(qf[i].w, cur[i].w, dot);
        }
        float score = warp_sum(dot) * NORM_CONST;

        float mn = fmaxf(m, score);
        float corr = __expf(m - mn);       // first row: exp(-inf)=0
        float w = __expf(score - mn);
        l = l * corr + w;
        #pragma unroll
        for (int i = 0; i < 6; i++) {
            acc[i].x = fmaf(w, cur[i].x, acc[i].x * corr);
            acc[i].y = fmaf(w, cur[i].y, acc[i].y * corr);
            acc[i].z = fmaf(w, cur[i].z, acc[i].z * corr);
            acc[i].w = fmaf(w, cur[i].w, acc[i].w * corr);
        }
        m = mn;
        __syncthreads();   // protect stage before next refill
    }

    // in-block merge of 8 warp partials -> 1 block partial
    float4* accsm = smem4;   // reuse stage memory (all stages consumed; sync above)
    #pragma unroll
    for (int i = 0; i < 6; i++) accsm[warp * D4 + i * 32 + lane] = acc[i];
    if (lane == 0) { msm[warp] = m; lsm[warp] = l; }
    __syncthreads();

    if (tid < D4) {
        float M = -CUDART_INF_F;
        #pragma unroll
        for (int w = 0; w < 8; w++) M = fmaxf(M, msm[w]);
        float L = 0.f;
        float4 s = make_float4(0.f, 0.f, 0.f, 0.f);
        #pragma unroll
        for (int w = 0; w < 8; w++) {
            float ef = __expf(msm[w] - M);
            L = fmaf(ef, lsm[w], L);
            float4 a = accsm[w * D4 + tid];
            s.x = fmaf(ef, a.x, s.x);
            s.y = fmaf(ef, a.y, s.y);
            s.z = fmaf(ef, a.z, s.z);
            s.w = fmaf(ef, a.w, s.w);
        }
        ((float4*)g_pacc)[(size_t)blockIdx.x * D4 + tid] = s;
        if (tid == 0) { g_pm[blockIdx.x] = M; g_pl[blockIdx.x] = L; }
    }
}

// ============ K3: split-softmax combine (16 partials/batch) ============
__global__ void __launch_bounds__(256) combine2(float* __restrict__ c)
{
    int b = blockIdx.y;
    int d = blockIdx.x * 256 + threadIdx.x;
    const float* pm = g_pm + b * CHUNKS_PER_B;
    const float* pl = g_pl + b * CHUNKS_PER_B;

    float M = -CUDART_INF_F;
    #pragma unroll
    for (int j = 0; j < CHUNKS_PER_B; j++) M = fmaxf(M, pm[j]);

    float L = 0.f, s = 0.f;
    #pragma unroll
    for (int j = 0; j < CHUNKS_PER_B; j++) {
        float ef = __expf(pm[j] - M);
        L = fmaf(ef, pl[j], L);
        s = fmaf(ef, g_pacc[((size_t)(b * CHUNKS_PER_B + j)) * Dn + d], s);
    }
    c[b * Dn + d] = s / L;
}

// ============ K4: out[b][e] = Wv[e][:] . c[b][:]  ============
// 96 blocks x 8 warps, warp = one e-row; c preloaded via cp.async float4
// (12/thread, one latency exposure), overlapped with Wv register loads.
__global__ void __launch_bounds__(256) matvec_wv(
    float* __restrict__ out, const float* __restrict__ W,
    const float* __restrict__ X)
{
    extern __shared__ float xs[];             // 48 KB: c for all 16 batches
    int tid = threadIdx.x, warp = tid >> 5, lane = tid & 31;

    {
        unsigned int sb = (unsigned int)__cvta_generic_to_shared(xs);
        const float4* src4 = (const float4*)X;
        #pragma unroll
        for (int i = 0; i < 12; i++) {
            int idx = i * 256 + tid;          // 0..3071 float4
            cp_async16(sb + idx * 16, src4 + idx);
        }
        cp_commit();
    }

    int e = blockIdx.x * 8 + warp;
    const float4* wr = (const float4*)(W + (size_t)e * Dn);
    float4 wf[6];
    #pragma unroll
    for (int i = 0; i < 6; i++) wf[i] = wr[i * 32 + lane];

    cp_wait_all();
    __syncthreads();

    const float4* xs4 = (const float4*)xs;
    float acc[Bn];
    #pragma unroll
    for (int b = 0; b < Bn; b++) acc[b] = 0.f;
    #pragma unroll
    for (int i = 0; i < 6; i++) {
        float4 w = wf[i];
        #pragma unroll
        for (int b = 0; b < Bn; b++) {
            float4 x = xs4[b * D4 + i * 32 + lane];
            acc[b] = fmaf(w.x, x.x, fmaf(w.y, x.y, fmaf(w.z, x.z, fmaf(w.w, x.w, acc[b]))));
        }
    }
    #pragma unroll
    for (int b = 0; b < Bn; b++) {
        float v = warp_sum(acc[b]);
        if (lane == 0) out[b * Dn + e] = v;
    }
}

// ---------------- launch ----------------
extern "C" void kernel_launch(void* const* d_in, const int* in_sizes, int n_in,
                              void* d_out, int out_size)
{
    const float* b_in = (const float*)d_in[0];
    // d_in[1] = mask (int64): masks whole QUERY rows only; query row 0 is always
    // unmasked and the output only uses query row 0 -> mask is irrelevant.
    const float* Wq = (const float*)d_in[2];
    const float* Wk = (const float*)d_in[3];
    const float* Wv = (const float*)d_in[4];
    float* out = (float*)d_out;

    float* qk; cudaGetSymbolAddress((void**)&qk, g_qk);
    float* cc; cudaGetSymbolAddress((void**)&cc, g_c);

    cudaFuncSetAttribute(fused_q0qk, cudaFuncAttributeMaxDynamicSharedMemorySize, 49152);
    cudaFuncSetAttribute(attn_stream, cudaFuncAttributeMaxDynamicSharedMemorySize, ATT_STAGES * STAGE_BYTES);
    cudaFuncSetAttribute(matvec_wv, cudaFuncAttributeMaxDynamicSharedMemorySize, 49152);

    cudaMemsetAsync(qk, 0, Bn * Dn * sizeof(float), 0);
    fused_q0qk<<<96, 256, 49152>>>(qk, Wq, Wk, b_in);
    attn_stream<<<NPART, 256, ATT_STAGES * STAGE_BYTES>>>(b_in, qk);
    combine2<<<dim3(3, Bn), 256>>>(cc);
    matvec_wv<<<96, 256, 49152>>>(out, Wv, cc);
}